// round 15
// baseline (speedup 1.0000x reference)
#include <cuda_runtime.h>
#include <cuda_fp16.h>
#include <math.h>
#include <stdint.h>

#define TOK 8192
#define SEQB 4096
#define DDIM 2560
#define HEADS 10
#define BW 256
#define NC 32
#define CL 128
#define NGATE 5120   // interleaved: col 2j = ig_j, col 2j+1 = ag_j

// ---------------- scratch (static device globals; no allocation) ----------------
__device__ float  g_a [(size_t)TOK * DDIM];    // recurrence decay a_t (fp32)
__device__ __half g_xbh[(size_t)TOK * DDIM];   // x-branch (pre-conv) fp16
__device__ __half g_ybh[(size_t)TOK * DDIM];   // gelu(y-branch) fp16
__device__ __half g_coh[(size_t)TOK * DDIM];   // conv out fp16
__device__ __half g_nxs[(size_t)TOK * DDIM];   // normalized x (scan input) fp16
__device__ __half g_xh [(size_t)TOK * DDIM];   // X in half
__device__ __half g_nxh[(size_t)TOK * DDIM];   // h*y in half (final GEMM input)
__device__ __half g_wch[(size_t)NGATE * DDIM]; // [w_x rows ; w_y rows] K-major
__device__ __half g_woh[(size_t)DDIM * DDIM];
__device__ __half g_gwh[(size_t)NGATE * BW];   // INTERLEAVED ig/ag rows x 256 K-major
__device__ float  g_Aag[2 * NC * DDIM];
__device__ float  g_Hag[2 * NC * DDIM];
__device__ float  g_Hin[2 * NC * DDIM];
__device__ unsigned char g_reset[TOK];

// ---------------- fast math helpers ----------------
__device__ __forceinline__ float tanh_fast(float x) {
    float r;
    asm("tanh.approx.f32 %0, %1;" : "=f"(r) : "f"(x));
    return r;
}
__device__ __forceinline__ float sqrt_fast(float x) {
    float r;
    asm("sqrt.approx.f32 %0, %1;" : "=f"(r) : "f"(x));
    return r;
}
__device__ __forceinline__ float gelu_tanh(float x) {
    float inner = 0.7978845608028654f * (x + 0.044715f * x * x * x);
    return 0.5f * x * (1.0f + tanh_fast(inner));
}
__device__ __forceinline__ float softplusf(float x) {
    return (x > 20.0f) ? x : log1pf(expf(x));
}

// ---------------- async-copy / mma helpers (sm_80+ features only) ----------------
__device__ __forceinline__ uint32_t smem_u32(const void* p) {
    uint32_t a;
    asm("{ .reg .u64 t; cvta.to.shared.u64 t, %1; cvt.u32.u64 %0, t; }" : "=r"(a) : "l"(p));
    return a;
}
__device__ __forceinline__ void cp16(uint32_t dst, const void* src) {
    asm volatile("cp.async.ca.shared.global [%0], [%1], 16;" :: "r"(dst), "l"(src));
}
__device__ __forceinline__ void cp_commit() {
    asm volatile("cp.async.commit_group;" ::: "memory");
}
template <int N> __device__ __forceinline__ void cp_wait() {
    asm volatile("cp.async.wait_group %0;" :: "n"(N) : "memory");
}
__device__ __forceinline__ void mma_f16(float* c, const uint32_t* a, const uint32_t* b) {
    asm volatile(
        "mma.sync.aligned.m16n8k16.row.col.f32.f16.f16.f32 "
        "{%0,%1,%2,%3}, {%4,%5,%6,%7}, {%8,%9}, {%0,%1,%2,%3};"
        : "+f"(c[0]), "+f"(c[1]), "+f"(c[2]), "+f"(c[3])
        : "r"(a[0]), "r"(a[1]), "r"(a[2]), "r"(a[3]), "r"(b[0]), "r"(b[1]));
}
__device__ __forceinline__ void ldm_x4(uint32_t* r, uint32_t addr) {
    asm volatile("ldmatrix.sync.aligned.m8n8.x4.shared.b16 {%0,%1,%2,%3}, [%4];"
        : "=r"(r[0]), "=r"(r[1]), "=r"(r[2]), "=r"(r[3]) : "r"(addr));
}

// ---------------- one fused conversion kernel (all fp32->fp16 + reset mask) --------
#define XN4 (TOK * DDIM / 4)          // 5,242,880
#define WN4 (DDIM * DDIM / 4)         // 1,638,400
#define GN4 (DDIM * BW / 4)           // 163,840
#define CVT_TOTAL (XN4 + 3 * WN4 + 2 * GN4)

__global__ void convert_all(const float* __restrict__ x_in,
                            const float* __restrict__ w_x,
                            const float* __restrict__ w_y,
                            const float* __restrict__ w_out,
                            const float* __restrict__ ig_w,
                            const float* __restrict__ ag_w,
                            const int* __restrict__ pos32) {
    int i = blockIdx.x * 256 + threadIdx.x;
    if (i < TOK) {
        bool is64 = (pos32[1] == 0 && pos32[2] == 1);
        bool r;
        if (is64) r = (pos32[2 * i] == 0 && pos32[2 * i + 1] == 0);
        else      r = (pos32[i] == 0);
        g_reset[i] = r ? 1 : 0;
    }
    if (i >= CVT_TOTAL) return;
    const float* src;
    __half* dst;
    int o = i;
    size_t od;
    if (o < XN4) { src = x_in; dst = g_xh; od = o; }
    else {
        o -= XN4;
        if (o < WN4) { src = w_x; dst = g_wch; od = o; }
        else {
            o -= WN4;
            if (o < WN4) { src = w_y; dst = g_wch + (size_t)DDIM * DDIM; od = o; }
            else {
                o -= WN4;
                if (o < WN4) { src = w_out; dst = g_woh; od = o; }
                else {
                    o -= WN4;
                    if (o < GN4) {
                        // ig row j -> interleaved row 2j
                        src = ig_w; dst = g_gwh;
                        int j = o >> 6, rem = o & 63;      // 64 float4 per 256-row
                        od = (size_t)(2 * j) * 64 + rem;
                    } else {
                        o -= GN4;
                        // ag row j -> interleaved row 2j+1
                        src = ag_w; dst = g_gwh;
                        int j = o >> 6, rem = o & 63;
                        od = (size_t)(2 * j + 1) * 64 + rem;
                    }
                }
            }
        }
    }
    float4 v = ((const float4*)src)[o];
    ((__half2*)dst)[2 * od]     = __floats2half2_rn(v.x, v.y);
    ((__half2*)dst)[2 * od + 1] = __floats2half2_rn(v.z, v.w);
}

// =======================================================================
// fp16 mma.sync GEMM, CTA tile 128(M) x 256(N), 8 warps (256 thr),
// warp tile 64x64 (2x4), K-chunk 64 halves, 3-stage cp.async,
// XOR-swizzled smem, fragment double-buffering (frozen mainloop).
// modes: 0 = fp32 out + bias (final)
//        1 = xy-combined: col<2560 -> g_xbh fp16 (+b_x); else gelu -> g_ybh
//        2 = gates (interleaved ig/ag) + FUSED RG-LRU pointwise +
//            chunk-scan phase 1 in the epilogue (M-tile == one chunk)
// =======================================================================
#define STG_B 49152                 // 16KB A + 32KB B per stage
#define GSMEM (3 * STG_B)           // 144 KB

// epilogue smem layout (mode 2): a_s [128][132] f32, nx_s/co_s [128][136] f16
#define AS_STR 132
#define HS_STR 136
#define AS_BYTES (128 * AS_STR * 4)          // 67584
#define HS_BYTES (128 * HS_STR * 2)          // 34816

__global__ __launch_bounds__(256, 1) void gemm_f16(
    const __half* __restrict__ A,
    const __half* __restrict__ W,
    const float* __restrict__ bias,
    const float* __restrict__ bias2,
    const float* __restrict__ aparam,
    float* __restrict__ outf,
    int K, int ldW, int ldc, int mode)
{
    extern __shared__ __align__(16) char smem[];
    const uint32_t sbase = smem_u32(smem);

    const int tid = threadIdx.x;
    const int lane = tid & 31;
    const int wid = tid >> 5;
    const int wm = wid & 1;          // 0..1 -> 64-row slice
    const int wn = wid >> 1;         // 0..3 -> 64-col slice
    const int m0 = blockIdx.y * 128;
    const int n0 = blockIdx.x * 256;
    const int aoff = (mode == 2) ? ((n0 >> 9) << 8) : 0;  // head(n0)*256
    const int NKC = K >> 6;

    const int lrow32 = tid >> 3;     // 0..31 (cp.async row base)
    const int chk    = tid & 7;      // 16B chunk within 128B row

    float acc[4][8][4];
#pragma unroll
    for (int i = 0; i < 4; i++)
#pragma unroll
        for (int j = 0; j < 8; j++)
#pragma unroll
            for (int q = 0; q < 4; q++) acc[i][j][q] = 0.0f;

#define LD_STAGE(s, kc)                                                           \
    {                                                                             \
        int ka = aoff + (kc) * 64 + chk * 8;                                      \
        int kb = (kc) * 64 + chk * 8;                                             \
        uint32_t sA = sbase + (s) * STG_B;                                        \
        uint32_t sB = sA + 16384;                                                 \
        _Pragma("unroll")                                                         \
        for (int i = 0; i < 4; i++) {                                             \
            int row = lrow32 + i * 32;                                            \
            cp16(sA + row * 128 + (((chk ^ row) & 7) << 4),                       \
                 A + (size_t)(m0 + row) * DDIM + ka);                             \
        }                                                                         \
        _Pragma("unroll")                                                         \
        for (int i = 0; i < 8; i++) {                                             \
            int row = lrow32 + i * 32;                                            \
            cp16(sB + row * 128 + (((chk ^ row) & 7) << 4),                       \
                 W + (size_t)(n0 + row) * ldW + kb);                              \
        }                                                                         \
        cp_commit();                                                              \
    }

    LD_STAGE(0, 0);
    LD_STAGE(1, 1);

    const int l15 = lane & 15;
    const int kbs = (lane >> 4) & 1;
    int rowA128[4], rowA7[4], rowB128[4], rowB7[4];
#pragma unroll
    for (int i = 0; i < 4; i++) {
        int ra = wm * 64 + i * 16 + l15;
        rowA128[i] = ra * 128; rowA7[i] = ra & 7;
        int rb = wn * 64 + i * 16 + l15;
        rowB128[i] = rb * 128 + 16384; rowB7[i] = rb & 7;
    }

    const int g = lane >> 2;
    const int t2 = (lane & 3) * 2;

    uint32_t af[2][4][4];
    uint32_t bf[2][8][2];

#define LDFRAG(St, ksg, B)                                                        \
    {                                                                             \
        _Pragma("unroll")                                                         \
        for (int i = 0; i < 4; i++)                                               \
            ldm_x4(af[B][i], (St) + rowA128[i] + ((((ksg) ^ rowA7[i]) & 7) << 4));\
        _Pragma("unroll")                                                         \
        for (int jp = 0; jp < 4; jp++) {                                          \
            uint32_t t[4];                                                        \
            ldm_x4(t, (St) + rowB128[jp] + ((((ksg) ^ rowB7[jp]) & 7) << 4));     \
            bf[B][2 * jp][0] = t[0]; bf[B][2 * jp + 1][0] = t[1];                 \
            bf[B][2 * jp][1] = t[2]; bf[B][2 * jp + 1][1] = t[3];                 \
        }                                                                         \
    }

    for (int kc = 0; kc < NKC; kc++) {
        cp_wait<1>();
        __syncthreads();
        int nxt = kc + 2;
        if (nxt < NKC) {
            LD_STAGE(nxt % 3, nxt);
        } else {
            cp_commit();
        }
        const uint32_t St = sbase + (kc % 3) * STG_B;
        LDFRAG(St, kbs, 0);
#pragma unroll
        for (int ks = 0; ks < 4; ks++) {
            const int cur = ks & 1;
            if (ks < 3) LDFRAG(St, (ks + 1) * 2 + kbs, cur ^ 1);
#pragma unroll
            for (int i = 0; i < 4; i++)
#pragma unroll
                for (int j = 0; j < 8; j++)
                    mma_f16(acc[i][j], af[cur][i], bf[cur][j]);
        }
    }

    if (mode == 2) {
        // ---- fused RG-LRU pointwise + chunk-scan phase 1 ----
        cp_wait<0>();
        __syncthreads();                       // all smem reads done -> reuse
        float*  a_s  = (float*)smem;                       // [128][132]
        __half* nx_s = (__half*)(smem + AS_BYTES);         // [128][136]
        __half* co_s = (__half*)(smem + AS_BYTES + HS_BYTES);
        const int d0g = n0 >> 1;               // global d of local col 0

        // stage conv-out tile [128 rows x 128 d] (coalesced 16B loads)
        for (int it = tid; it < 128 * 16; it += 256) {
            int row = it >> 4, ch = it & 15;
            *(uint4*)(co_s + row * HS_STR + ch * 8) =
                *(const uint4*)(g_coh + (size_t)(m0 + row) * DDIM + d0g + ch * 8);
        }
        __syncthreads();

        // pointwise: each thread owns (ig, ag) pairs for one d per (i,j)
#pragma unroll
        for (int j = 0; j < 8; j++) {
            int dl = (wn * 64 + j * 8 + t2) >> 1;   // local d 0..127
            int dg = d0g + dl;
            float bi = bias [dg & 255];
            float ba = bias2[dg & 255];
            float sp8 = -8.0f * softplusf(aparam[dg]);
#pragma unroll
            for (int i = 0; i < 4; i++) {
#pragma unroll
                for (int h = 0; h < 2; h++) {
                    int rl = wm * 64 + i * 16 + g + h * 8;
                    float li = acc[i][j][h * 2 + 0] + bi;
                    float la = acc[i][j][h * 2 + 1] + ba;
                    bool rs = (g_reset[m0 + rl] != 0);
                    float gx = 0.5f + 0.5f * tanh_fast(0.5f * li);
                    float ga = __fdividef(1.0f, 1.0f + __expf(-la));
                    float log_a = ga * sp8;
                    float a = rs ? 0.0f : __expf(log_a);
                    float mult = rs ? 1.0f : sqrt_fast(fmaxf(1.0f - a * a, 0.0f));
                    float co = __half2float(co_s[rl * HS_STR + dl]);
                    float nx = co * gx * mult;
                    a_s[rl * AS_STR + dl] = a;
                    nx_s[rl * HS_STR + dl] = __float2half(nx);
                }
            }
        }
        __syncthreads();

        // coalesced writeback of a (fp32) and nx (fp16)
        for (int it = tid; it < 128 * 32; it += 256) {
            int row = it >> 5, ch = it & 31;
            *(float4*)(g_a + (size_t)(m0 + row) * DDIM + d0g + ch * 4) =
                *(const float4*)(a_s + row * AS_STR + ch * 4);
        }
        for (int it = tid; it < 128 * 16; it += 256) {
            int row = it >> 4, ch = it & 15;
            *(uint4*)(g_nxs + (size_t)(m0 + row) * DDIM + d0g + ch * 8) =
                *(const uint4*)(nx_s + row * HS_STR + ch * 8);
        }

        // chunk-scan phase 1: one thread per d
        if (tid < 128) {
            int dl = tid;
            float Ag = 1.0f, Hg = 0.0f;
#pragma unroll 4
            for (int r = 0; r < 128; r++) {
                float a = a_s[r * AS_STR + dl];
                float nx = __half2float(nx_s[r * HS_STR + dl]);
                Hg = fmaf(a, Hg, nx);
                Ag *= a;
            }
            int bb = m0 >> 12;                // batch
            int cc = (m0 & 4095) >> 7;        // chunk
            int oo = (bb * NC + cc) * DDIM + d0g + dl;
            g_Aag[oo] = Ag;
            g_Hag[oo] = Hg;
        }
        return;
    }

    // ---- default epilogue (modes 0 / 1) ----
#pragma unroll
    for (int i = 0; i < 4; i++) {
        int r = m0 + wm * 64 + i * 16 + g;
#pragma unroll
        for (int j = 0; j < 8; j++) {
            int col = n0 + wn * 64 + j * 8 + t2;
            float v00 = acc[i][j][0], v01 = acc[i][j][1];
            float v10 = acc[i][j][2], v11 = acc[i][j][3];
            if (mode == 0) {
                float b0 = bias[col], b1 = bias[col + 1];
                *(float2*)(outf + (size_t)r * ldc + col)       = make_float2(v00 + b0, v01 + b1);
                *(float2*)(outf + (size_t)(r + 8) * ldc + col) = make_float2(v10 + b0, v11 + b1);
            } else {
                if (col < DDIM) {
                    float b0 = bias[col], b1 = bias[col + 1];
                    *(__half2*)(g_xbh + (size_t)r * DDIM + col) =
                        __floats2half2_rn(v00 + b0, v01 + b1);
                    *(__half2*)(g_xbh + (size_t)(r + 8) * DDIM + col) =
                        __floats2half2_rn(v10 + b0, v11 + b1);
                } else {
                    int c2 = col - DDIM;
                    float b0 = bias2[c2], b1 = bias2[c2 + 1];
                    *(__half2*)(g_ybh + (size_t)r * DDIM + c2) =
                        __floats2half2_rn(gelu_tanh(v00 + b0), gelu_tanh(v01 + b1));
                    *(__half2*)(g_ybh + (size_t)(r + 8) * DDIM + c2) =
                        __floats2half2_rn(gelu_tanh(v10 + b0), gelu_tanh(v11 + b1));
                }
            }
        }
    }
}

// ---------------- depthwise causal conv (fp16 in/out), 4 timesteps/thread ----------------
__global__ __launch_bounds__(256) void conv_kernel(const float* __restrict__ cw,
                                                   const float* __restrict__ cb) {
    const int D4 = DDIM / 4;             // 640 groups of 4 halves
    const int TB = SEQB / 4;             // 1024
    int idx = blockIdx.x * 256 + threadIdx.x;
    if (idx >= 2 * TB * D4) return;
    int d4 = idx % D4;
    int tb = (idx / D4) % TB;
    int b  = idx / (D4 * TB);
    int t0 = tb * 4;
    int d0 = d4 * 4;

    float cwv[4][4];
#pragma unroll
    for (int e = 0; e < 4; e++)
#pragma unroll
        for (int k = 0; k < 4; k++) cwv[e][k] = cw[(d0 + e) * 4 + k];
    float4 cb4 = *(const float4*)(cb + d0);

    const __half2* X2 = (const __half2*)g_xbh;
    float4 xv[7];
#pragma unroll
    for (int i = 0; i < 7; i++) {
        int t = t0 + i - 3;
        if (t >= 0) {
            size_t o = ((size_t)(b * SEQB + t)) * (DDIM / 2) + d4 * 2;
            __half2 h0 = X2[o], h1 = X2[o + 1];
            xv[i] = make_float4(__low2float(h0), __high2float(h0),
                                __low2float(h1), __high2float(h1));
        } else {
            xv[i] = make_float4(0.f, 0.f, 0.f, 0.f);
        }
    }

#pragma unroll
    for (int jj = 0; jj < 4; jj++) {
        float4 acc = cb4;
#pragma unroll
        for (int k = 0; k < 4; k++) {
            acc.x = fmaf(xv[jj + k].x, cwv[0][k], acc.x);
            acc.y = fmaf(xv[jj + k].y, cwv[1][k], acc.y);
            acc.z = fmaf(xv[jj + k].z, cwv[2][k], acc.z);
            acc.w = fmaf(xv[jj + k].w, cwv[3][k], acc.w);
        }
        size_t o = ((size_t)(b * SEQB + t0 + jj)) * (DDIM / 2) + d4 * 2;
        ((__half2*)g_coh)[o]     = __floats2half2_rn(acc.x, acc.y);
        ((__half2*)g_coh)[o + 1] = __floats2half2_rn(acc.z, acc.w);
    }
}

// ---------------- cross-chunk scan ----------------
__global__ __launch_bounds__(256) void scan_phase2(const float* __restrict__ prev_h) {
    int t = blockIdx.x * 256 + threadIdx.x;
    if (t >= 2 * DDIM) return;
    int b = t / DDIM, d = t % DDIM;
    float h = prev_h[t];
#pragma unroll
    for (int c = 0; c < NC; c++) {
        int o = (b * NC + c) * DDIM + d;
        g_Hin[o] = h;
        h = fmaf(g_Aag[o], h, g_Hag[o]);
    }
}

__global__ __launch_bounds__(256) void scan_phase3() {
    int d = blockIdx.x * 256 + threadIdx.x;
    int c = blockIdx.y;
    int b = blockIdx.z;
    int base = (b * SEQB + c * CL) * DDIM + d;
    float h = g_Hin[(b * NC + c) * DDIM + d];
#pragma unroll 4
    for (int i = 0; i < CL; i++) {
        int o = base + i * DDIM;
        float a = g_a[o];
        float x = __half2float(g_nxs[o]);
        h = fmaf(a, h, x);
        g_nxh[o] = __float2half(h * __half2float(g_ybh[o]));
    }
}

// ---------------- launcher ----------------
extern "C" void kernel_launch(void* const* d_in, const int* in_sizes, int n_in,
                              void* d_out, int out_size) {
    const float* x_in    = (const float*)d_in[0];
    const int*   pos     = (const int*)d_in[1];
    const float* prev_h  = (const float*)d_in[2];
    const float* w_y     = (const float*)d_in[3];
    const float* b_y     = (const float*)d_in[4];
    const float* w_x     = (const float*)d_in[5];
    const float* b_x     = (const float*)d_in[6];
    const float* w_out   = (const float*)d_in[7];
    const float* b_out   = (const float*)d_in[8];
    const float* conv_w  = (const float*)d_in[9];
    const float* conv_b  = (const float*)d_in[10];
    const float* a_param = (const float*)d_in[11];
    const float* ig_w    = (const float*)d_in[12];
    const float* ig_b    = (const float*)d_in[13];
    const float* ag_w    = (const float*)d_in[14];
    const float* ag_b    = (const float*)d_in[15];
    float* out = (float*)d_out;

    __half *p_xh, *p_coh, *p_nxh, *p_wch, *p_woh, *p_gwh;
    cudaGetSymbolAddress((void**)&p_xh,  g_xh);
    cudaGetSymbolAddress((void**)&p_coh, g_coh);
    cudaGetSymbolAddress((void**)&p_nxh, g_nxh);
    cudaGetSymbolAddress((void**)&p_wch, g_wch);
    cudaGetSymbolAddress((void**)&p_woh, g_woh);
    cudaGetSymbolAddress((void**)&p_gwh, g_gwh);

    cudaFuncSetAttribute(gemm_f16, cudaFuncAttributeMaxDynamicSharedMemorySize, GSMEM);

    // one fused conversion + reset kernel (gate weights interleaved)
    convert_all<<<(CVT_TOTAL + 255) / 256, 256>>>(x_in, w_x, w_y, w_out, ig_w, ag_w, pos);

    // combined x/y GEMM (N = 5120): writes g_xbh (fp16) and g_ybh (fp16, gelu)
    dim3 gxy(NGATE / 256, TOK / 128);   // (20, 64)
    gemm_f16<<<gxy, 256, GSMEM>>>(p_xh, p_wch, b_x, b_y, nullptr, nullptr,
                                  DDIM, DDIM, 0, 1);

    // conv (fp16 in, fp16 out)
    conv_kernel<<<(2 * (SEQB / 4) * (DDIM / 4) + 255) / 256, 256>>>(conv_w, conv_b);

    // gates GEMM (interleaved ig/ag) + fused RG-LRU pointwise + scan phase 1
    gemm_f16<<<gxy, 256, GSMEM>>>(p_coh, p_gwh, ig_b, ag_b, a_param, nullptr,
                                  BW, BW, 0, 2);

    // cross-chunk scan + fix-up
    scan_phase2<<<(2 * DDIM + 255) / 256, 256>>>(prev_h);
    scan_phase3<<<dim3(DDIM / 256, NC, 2), 256>>>();

    // final GEMM
    dim3 gf(DDIM / 256, TOK / 128);     // (10, 64)
    gemm_f16<<<gf, 256, GSMEM>>>(p_nxh, p_woh, b_out, nullptr, nullptr, out,
                                 DDIM, DDIM, DDIM, 0);
}

// round 16
// speedup vs baseline: 1.0101x; 1.0101x over previous
#include <cuda_runtime.h>
#include <cuda_fp16.h>
#include <math.h>
#include <stdint.h>

#define TOK 8192
#define SEQB 4096
#define DDIM 2560
#define HEADS 10
#define BW 256
#define NC 32
#define CL 128
#define NGATE 5120   // interleaved: col 2j = ig_j, col 2j+1 = ag_j

// ---------------- scratch (static device globals; no allocation) ----------------
__device__ __half g_ah [(size_t)TOK * DDIM];   // recurrence decay a_t (fp16; a<=0.6 typ, amplification bounded)
__device__ __half g_xbh[(size_t)TOK * DDIM];   // x-branch (pre-conv) fp16
__device__ __half g_ybh[(size_t)TOK * DDIM];   // gelu(y-branch) fp16
__device__ __half g_coh[(size_t)TOK * DDIM];   // conv out fp16
__device__ __half g_nxs[(size_t)TOK * DDIM];   // normalized x (scan input) fp16
__device__ __half g_xh [(size_t)TOK * DDIM];   // X in half
__device__ __half g_nxh[(size_t)TOK * DDIM];   // h*y in half (final GEMM input)
__device__ __half g_wch[(size_t)NGATE * DDIM]; // [w_x rows ; w_y rows] K-major
__device__ __half g_woh[(size_t)DDIM * DDIM];
__device__ __half g_gwh[(size_t)NGATE * BW];   // INTERLEAVED ig/ag rows x 256 K-major
__device__ float  g_Aag[2 * NC * DDIM];
__device__ float  g_Hag[2 * NC * DDIM];
__device__ float  g_Hin[2 * NC * DDIM];
__device__ unsigned char g_reset[TOK];

// ---------------- fast math helpers ----------------
__device__ __forceinline__ float tanh_fast(float x) {
    float r;
    asm("tanh.approx.f32 %0, %1;" : "=f"(r) : "f"(x));
    return r;
}
__device__ __forceinline__ float sqrt_fast(float x) {
    float r;
    asm("sqrt.approx.f32 %0, %1;" : "=f"(r) : "f"(x));
    return r;
}
__device__ __forceinline__ float gelu_tanh(float x) {
    float inner = 0.7978845608028654f * (x + 0.044715f * x * x * x);
    return 0.5f * x * (1.0f + tanh_fast(inner));
}
__device__ __forceinline__ float softplusf(float x) {
    return (x > 20.0f) ? x : log1pf(expf(x));
}

// ---------------- async-copy / mma helpers (sm_80+ features only) ----------------
__device__ __forceinline__ uint32_t smem_u32(const void* p) {
    uint32_t a;
    asm("{ .reg .u64 t; cvta.to.shared.u64 t, %1; cvt.u32.u64 %0, t; }" : "=r"(a) : "l"(p));
    return a;
}
__device__ __forceinline__ void cp16(uint32_t dst, const void* src) {
    asm volatile("cp.async.ca.shared.global [%0], [%1], 16;" :: "r"(dst), "l"(src));
}
__device__ __forceinline__ void cp_commit() {
    asm volatile("cp.async.commit_group;" ::: "memory");
}
template <int N> __device__ __forceinline__ void cp_wait() {
    asm volatile("cp.async.wait_group %0;" :: "n"(N) : "memory");
}
__device__ __forceinline__ void mma_f16(float* c, const uint32_t* a, const uint32_t* b) {
    asm volatile(
        "mma.sync.aligned.m16n8k16.row.col.f32.f16.f16.f32 "
        "{%0,%1,%2,%3}, {%4,%5,%6,%7}, {%8,%9}, {%0,%1,%2,%3};"
        : "+f"(c[0]), "+f"(c[1]), "+f"(c[2]), "+f"(c[3])
        : "r"(a[0]), "r"(a[1]), "r"(a[2]), "r"(a[3]), "r"(b[0]), "r"(b[1]));
}
__device__ __forceinline__ void ldm_x4(uint32_t* r, uint32_t addr) {
    asm volatile("ldmatrix.sync.aligned.m8n8.x4.shared.b16 {%0,%1,%2,%3}, [%4];"
        : "=r"(r[0]), "=r"(r[1]), "=r"(r[2]), "=r"(r[3]) : "r"(addr));
}

// ---------------- one fused conversion kernel (all fp32->fp16 + reset mask) --------
#define XN4 (TOK * DDIM / 4)          // 5,242,880
#define WN4 (DDIM * DDIM / 4)         // 1,638,400
#define GN4 (DDIM * BW / 4)           // 163,840
#define CVT_TOTAL (XN4 + 3 * WN4 + 2 * GN4)

__global__ void convert_all(const float* __restrict__ x_in,
                            const float* __restrict__ w_x,
                            const float* __restrict__ w_y,
                            const float* __restrict__ w_out,
                            const float* __restrict__ ig_w,
                            const float* __restrict__ ag_w,
                            const int* __restrict__ pos32) {
    int i = blockIdx.x * 256 + threadIdx.x;
    if (i < TOK) {
        bool is64 = (pos32[1] == 0 && pos32[2] == 1);
        bool r;
        if (is64) r = (pos32[2 * i] == 0 && pos32[2 * i + 1] == 0);
        else      r = (pos32[i] == 0);
        g_reset[i] = r ? 1 : 0;
    }
    if (i >= CVT_TOTAL) return;
    const float* src;
    __half* dst;
    int o = i;
    size_t od;
    if (o < XN4) { src = x_in; dst = g_xh; od = o; }
    else {
        o -= XN4;
        if (o < WN4) { src = w_x; dst = g_wch; od = o; }
        else {
            o -= WN4;
            if (o < WN4) { src = w_y; dst = g_wch + (size_t)DDIM * DDIM; od = o; }
            else {
                o -= WN4;
                if (o < WN4) { src = w_out; dst = g_woh; od = o; }
                else {
                    o -= WN4;
                    if (o < GN4) {
                        // ig row j -> interleaved row 2j
                        src = ig_w; dst = g_gwh;
                        int j = o >> 6, rem = o & 63;
                        od = (size_t)(2 * j) * 64 + rem;
                    } else {
                        o -= GN4;
                        // ag row j -> interleaved row 2j+1
                        src = ag_w; dst = g_gwh;
                        int j = o >> 6, rem = o & 63;
                        od = (size_t)(2 * j + 1) * 64 + rem;
                    }
                }
            }
        }
    }
    float4 v = ((const float4*)src)[o];
    ((__half2*)dst)[2 * od]     = __floats2half2_rn(v.x, v.y);
    ((__half2*)dst)[2 * od + 1] = __floats2half2_rn(v.z, v.w);
}

// =======================================================================
// fp16 mma.sync GEMM, CTA tile 128(M) x 256(N), 8 warps (256 thr),
// warp tile 64x64 (2x4), K-chunk 64 halves, 3-stage cp.async,
// XOR-swizzled smem, fragment double-buffering (frozen mainloop).
// modes: 0 = fp32 out + bias (final)
//        1 = xy-combined: col<2560 -> g_xbh fp16 (+b_x); else gelu -> g_ybh
//        2 = gates (interleaved ig/ag) + FUSED RG-LRU pointwise +
//            2x-parallel chunk-scan phase 1 (all-fp16 staging)
// =======================================================================
#define STG_B 49152                 // 16KB A + 32KB B per stage
#define GSMEM (3 * STG_B)           // 144 KB

// mode-2 epilogue smem: three half tiles [128][136] + combine scratch
#define HS_STR 136
#define HS_BYTES (128 * HS_STR * 2)          // 34816
#define PART_OFF (3 * HS_BYTES)              // 104448

__global__ __launch_bounds__(256, 1) void gemm_f16(
    const __half* __restrict__ A,
    const __half* __restrict__ W,
    const float* __restrict__ bias,
    const float* __restrict__ bias2,
    const float* __restrict__ aparam,
    float* __restrict__ outf,
    int K, int ldW, int ldc, int mode)
{
    extern __shared__ __align__(16) char smem[];
    const uint32_t sbase = smem_u32(smem);

    const int tid = threadIdx.x;
    const int lane = tid & 31;
    const int wid = tid >> 5;
    const int wm = wid & 1;          // 0..1 -> 64-row slice
    const int wn = wid >> 1;         // 0..3 -> 64-col slice
    const int m0 = blockIdx.y * 128;
    const int n0 = blockIdx.x * 256;
    const int aoff = (mode == 2) ? ((n0 >> 9) << 8) : 0;  // head(n0)*256
    const int NKC = K >> 6;

    const int lrow32 = tid >> 3;     // 0..31 (cp.async row base)
    const int chk    = tid & 7;      // 16B chunk within 128B row

    float acc[4][8][4];
#pragma unroll
    for (int i = 0; i < 4; i++)
#pragma unroll
        for (int j = 0; j < 8; j++)
#pragma unroll
            for (int q = 0; q < 4; q++) acc[i][j][q] = 0.0f;

#define LD_STAGE(s, kc)                                                           \
    {                                                                             \
        int ka = aoff + (kc) * 64 + chk * 8;                                      \
        int kb = (kc) * 64 + chk * 8;                                             \
        uint32_t sA = sbase + (s) * STG_B;                                        \
        uint32_t sB = sA + 16384;                                                 \
        _Pragma("unroll")                                                         \
        for (int i = 0; i < 4; i++) {                                             \
            int row = lrow32 + i * 32;                                            \
            cp16(sA + row * 128 + (((chk ^ row) & 7) << 4),                       \
                 A + (size_t)(m0 + row) * DDIM + ka);                             \
        }                                                                         \
        _Pragma("unroll")                                                         \
        for (int i = 0; i < 8; i++) {                                             \
            int row = lrow32 + i * 32;                                            \
            cp16(sB + row * 128 + (((chk ^ row) & 7) << 4),                       \
                 W + (size_t)(n0 + row) * ldW + kb);                              \
        }                                                                         \
        cp_commit();                                                              \
    }

    LD_STAGE(0, 0);
    LD_STAGE(1, 1);

    const int l15 = lane & 15;
    const int kbs = (lane >> 4) & 1;
    int rowA128[4], rowA7[4], rowB128[4], rowB7[4];
#pragma unroll
    for (int i = 0; i < 4; i++) {
        int ra = wm * 64 + i * 16 + l15;
        rowA128[i] = ra * 128; rowA7[i] = ra & 7;
        int rb = wn * 64 + i * 16 + l15;
        rowB128[i] = rb * 128 + 16384; rowB7[i] = rb & 7;
    }

    const int g = lane >> 2;
    const int t2 = (lane & 3) * 2;

    uint32_t af[2][4][4];
    uint32_t bf[2][8][2];

#define LDFRAG(St, ksg, B)                                                        \
    {                                                                             \
        _Pragma("unroll")                                                         \
        for (int i = 0; i < 4; i++)                                               \
            ldm_x4(af[B][i], (St) + rowA128[i] + ((((ksg) ^ rowA7[i]) & 7) << 4));\
        _Pragma("unroll")                                                         \
        for (int jp = 0; jp < 4; jp++) {                                          \
            uint32_t t[4];                                                        \
            ldm_x4(t, (St) + rowB128[jp] + ((((ksg) ^ rowB7[jp]) & 7) << 4));     \
            bf[B][2 * jp][0] = t[0]; bf[B][2 * jp + 1][0] = t[1];                 \
            bf[B][2 * jp][1] = t[2]; bf[B][2 * jp + 1][1] = t[3];                 \
        }                                                                         \
    }

    for (int kc = 0; kc < NKC; kc++) {
        cp_wait<1>();
        __syncthreads();
        int nxt = kc + 2;
        if (nxt < NKC) {
            LD_STAGE(nxt % 3, nxt);
        } else {
            cp_commit();
        }
        const uint32_t St = sbase + (kc % 3) * STG_B;
        LDFRAG(St, kbs, 0);
#pragma unroll
        for (int ks = 0; ks < 4; ks++) {
            const int cur = ks & 1;
            if (ks < 3) LDFRAG(St, (ks + 1) * 2 + kbs, cur ^ 1);
#pragma unroll
            for (int i = 0; i < 4; i++)
#pragma unroll
                for (int j = 0; j < 8; j++)
                    mma_f16(acc[i][j], af[cur][i], bf[cur][j]);
        }
    }

    if (mode == 2) {
        // ---- fused RG-LRU pointwise + 2x-parallel chunk-scan phase 1 ----
        cp_wait<0>();
        __syncthreads();
        __half* a_s  = (__half*)smem;                          // [128][136]
        __half* nx_s = (__half*)(smem + HS_BYTES);             // [128][136]
        __half* co_s = (__half*)(smem + 2 * HS_BYTES);         // [128][136]
        float*  pA   = (float*)(smem + PART_OFF);              // [2][128]
        float*  pH   = pA + 256;                               // [2][128]
        const int d0g = n0 >> 1;               // global d of local col 0

        // stage conv-out tile [128 rows x 128 d] (coalesced 16B loads)
        for (int it = tid; it < 128 * 16; it += 256) {
            int row = it >> 4, ch = it & 15;
            *(uint4*)(co_s + row * HS_STR + ch * 8) =
                *(const uint4*)(g_coh + (size_t)(m0 + row) * DDIM + d0g + ch * 8);
        }
        __syncthreads();

        // pointwise: each thread owns (ig, ag) pairs for one d per (i,j)
#pragma unroll
        for (int j = 0; j < 8; j++) {
            int dl = (wn * 64 + j * 8 + t2) >> 1;   // local d 0..127
            int dg = d0g + dl;
            float bi = bias [dg & 255];
            float ba = bias2[dg & 255];
            float sp8 = -8.0f * softplusf(aparam[dg]);
#pragma unroll
            for (int i = 0; i < 4; i++) {
#pragma unroll
                for (int h = 0; h < 2; h++) {
                    int rl = wm * 64 + i * 16 + g + h * 8;
                    float li = acc[i][j][h * 2 + 0] + bi;
                    float la = acc[i][j][h * 2 + 1] + ba;
                    bool rs = (g_reset[m0 + rl] != 0);
                    float gx = 0.5f + 0.5f * tanh_fast(0.5f * li);
                    float ga = __fdividef(1.0f, 1.0f + __expf(-la));
                    float log_a = ga * sp8;
                    float a = rs ? 0.0f : __expf(log_a);
                    float mult = rs ? 1.0f : sqrt_fast(fmaxf(1.0f - a * a, 0.0f));
                    float co = __half2float(co_s[rl * HS_STR + dl]);
                    float nx = co * gx * mult;
                    a_s[rl * HS_STR + dl]  = __float2half(a);
                    nx_s[rl * HS_STR + dl] = __float2half(nx);
                }
            }
        }
        __syncthreads();

        // coalesced writeback of a (fp16) and nx (fp16)
        for (int it = tid; it < 128 * 16; it += 256) {
            int row = it >> 4, ch = it & 15;
            *(uint4*)(g_ah + (size_t)(m0 + row) * DDIM + d0g + ch * 8) =
                *(const uint4*)(a_s + row * HS_STR + ch * 8);
            *(uint4*)(g_nxs + (size_t)(m0 + row) * DDIM + d0g + ch * 8) =
                *(const uint4*)(nx_s + row * HS_STR + ch * 8);
        }

        // phase 1: 2 threads per d, 64 rows each, then associative combine
        {
            int dl = tid & 127;
            int hf = tid >> 7;                 // segment 0 or 1
            float Aseg = 1.0f, Hseg = 0.0f;
            int r0 = hf * 64;
#pragma unroll 4
            for (int r = r0; r < r0 + 64; r++) {
                float a  = __half2float(a_s[r * HS_STR + dl]);
                float nx = __half2float(nx_s[r * HS_STR + dl]);
                Hseg = fmaf(a, Hseg, nx);
                Aseg *= a;
            }
            pA[hf * 128 + dl] = Aseg;
            pH[hf * 128 + dl] = Hseg;
        }
        __syncthreads();
        if (tid < 128) {
            float A0 = pA[tid],       H0 = pH[tid];
            float A1 = pA[128 + tid], H1 = pH[128 + tid];
            int bb = m0 >> 12;                // batch
            int cc = (m0 & 4095) >> 7;        // chunk
            int oo = (bb * NC + cc) * DDIM + d0g + tid;
            g_Aag[oo] = A0 * A1;
            g_Hag[oo] = fmaf(A1, H0, H1);
        }
        return;
    }

    // ---- default epilogue (modes 0 / 1) ----
#pragma unroll
    for (int i = 0; i < 4; i++) {
        int r = m0 + wm * 64 + i * 16 + g;
#pragma unroll
        for (int j = 0; j < 8; j++) {
            int col = n0 + wn * 64 + j * 8 + t2;
            float v00 = acc[i][j][0], v01 = acc[i][j][1];
            float v10 = acc[i][j][2], v11 = acc[i][j][3];
            if (mode == 0) {
                float b0 = bias[col], b1 = bias[col + 1];
                *(float2*)(outf + (size_t)r * ldc + col)       = make_float2(v00 + b0, v01 + b1);
                *(float2*)(outf + (size_t)(r + 8) * ldc + col) = make_float2(v10 + b0, v11 + b1);
            } else {
                if (col < DDIM) {
                    float b0 = bias[col], b1 = bias[col + 1];
                    *(__half2*)(g_xbh + (size_t)r * DDIM + col) =
                        __floats2half2_rn(v00 + b0, v01 + b1);
                    *(__half2*)(g_xbh + (size_t)(r + 8) * DDIM + col) =
                        __floats2half2_rn(v10 + b0, v11 + b1);
                } else {
                    int c2 = col - DDIM;
                    float b0 = bias2[c2], b1 = bias2[c2 + 1];
                    *(__half2*)(g_ybh + (size_t)r * DDIM + c2) =
                        __floats2half2_rn(gelu_tanh(v00 + b0), gelu_tanh(v01 + b1));
                    *(__half2*)(g_ybh + (size_t)(r + 8) * DDIM + c2) =
                        __floats2half2_rn(gelu_tanh(v10 + b0), gelu_tanh(v11 + b1));
                }
            }
        }
    }
}

// ---------------- depthwise causal conv (fp16 in/out), 4 timesteps/thread ----------------
__global__ __launch_bounds__(256) void conv_kernel(const float* __restrict__ cw,
                                                   const float* __restrict__ cb) {
    const int D4 = DDIM / 4;             // 640 groups of 4 halves
    const int TB = SEQB / 4;             // 1024
    int idx = blockIdx.x * 256 + threadIdx.x;
    if (idx >= 2 * TB * D4) return;
    int d4 = idx % D4;
    int tb = (idx / D4) % TB;
    int b  = idx / (D4 * TB);
    int t0 = tb * 4;
    int d0 = d4 * 4;

    float cwv[4][4];
#pragma unroll
    for (int e = 0; e < 4; e++)
#pragma unroll
        for (int k = 0; k < 4; k++) cwv[e][k] = cw[(d0 + e) * 4 + k];
    float4 cb4 = *(const float4*)(cb + d0);

    const __half2* X2 = (const __half2*)g_xbh;
    float4 xv[7];
#pragma unroll
    for (int i = 0; i < 7; i++) {
        int t = t0 + i - 3;
        if (t >= 0) {
            size_t o = ((size_t)(b * SEQB + t)) * (DDIM / 2) + d4 * 2;
            __half2 h0 = X2[o], h1 = X2[o + 1];
            xv[i] = make_float4(__low2float(h0), __high2float(h0),
                                __low2float(h1), __high2float(h1));
        } else {
            xv[i] = make_float4(0.f, 0.f, 0.f, 0.f);
        }
    }

#pragma unroll
    for (int jj = 0; jj < 4; jj++) {
        float4 acc = cb4;
#pragma unroll
        for (int k = 0; k < 4; k++) {
            acc.x = fmaf(xv[jj + k].x, cwv[0][k], acc.x);
            acc.y = fmaf(xv[jj + k].y, cwv[1][k], acc.y);
            acc.z = fmaf(xv[jj + k].z, cwv[2][k], acc.z);
            acc.w = fmaf(xv[jj + k].w, cwv[3][k], acc.w);
        }
        size_t o = ((size_t)(b * SEQB + t0 + jj)) * (DDIM / 2) + d4 * 2;
        ((__half2*)g_coh)[o]     = __floats2half2_rn(acc.x, acc.y);
        ((__half2*)g_coh)[o + 1] = __floats2half2_rn(acc.z, acc.w);
    }
}

// ---------------- cross-chunk scan ----------------
__global__ __launch_bounds__(256) void scan_phase2(const float* __restrict__ prev_h) {
    int t = blockIdx.x * 256 + threadIdx.x;
    if (t >= 2 * DDIM) return;
    int b = t / DDIM, d = t % DDIM;
    float h = prev_h[t];
#pragma unroll
    for (int c = 0; c < NC; c++) {
        int o = (b * NC + c) * DDIM + d;
        g_Hin[o] = h;
        h = fmaf(g_Aag[o], h, g_Hag[o]);
    }
}

__global__ __launch_bounds__(256) void scan_phase3() {
    int d = blockIdx.x * 256 + threadIdx.x;
    int c = blockIdx.y;
    int b = blockIdx.z;
    int base = (b * SEQB + c * CL) * DDIM + d;
    float h = g_Hin[(b * NC + c) * DDIM + d];
#pragma unroll 4
    for (int i = 0; i < CL; i++) {
        int o = base + i * DDIM;
        float a = __half2float(g_ah[o]);
        float x = __half2float(g_nxs[o]);
        h = fmaf(a, h, x);
        g_nxh[o] = __float2half(h * __half2float(g_ybh[o]));
    }
}

// ---------------- launcher ----------------
extern "C" void kernel_launch(void* const* d_in, const int* in_sizes, int n_in,
                              void* d_out, int out_size) {
    const float* x_in    = (const float*)d_in[0];
    const int*   pos     = (const int*)d_in[1];
    const float* prev_h  = (const float*)d_in[2];
    const float* w_y     = (const float*)d_in[3];
    const float* b_y     = (const float*)d_in[4];
    const float* w_x     = (const float*)d_in[5];
    const float* b_x     = (const float*)d_in[6];
    const float* w_out   = (const float*)d_in[7];
    const float* b_out   = (const float*)d_in[8];
    const float* conv_w  = (const float*)d_in[9];
    const float* conv_b  = (const float*)d_in[10];
    const float* a_param = (const float*)d_in[11];
    const float* ig_w    = (const float*)d_in[12];
    const float* ig_b    = (const float*)d_in[13];
    const float* ag_w    = (const float*)d_in[14];
    const float* ag_b    = (const float*)d_in[15];
    float* out = (float*)d_out;

    __half *p_xh, *p_coh, *p_nxh, *p_wch, *p_woh, *p_gwh;
    cudaGetSymbolAddress((void**)&p_xh,  g_xh);
    cudaGetSymbolAddress((void**)&p_coh, g_coh);
    cudaGetSymbolAddress((void**)&p_nxh, g_nxh);
    cudaGetSymbolAddress((void**)&p_wch, g_wch);
    cudaGetSymbolAddress((void**)&p_woh, g_woh);
    cudaGetSymbolAddress((void**)&p_gwh, g_gwh);

    cudaFuncSetAttribute(gemm_f16, cudaFuncAttributeMaxDynamicSharedMemorySize, GSMEM);

    // one fused conversion + reset kernel (gate weights interleaved)
    convert_all<<<(CVT_TOTAL + 255) / 256, 256>>>(x_in, w_x, w_y, w_out, ig_w, ag_w, pos);

    // combined x/y GEMM (N = 5120): writes g_xbh (fp16) and g_ybh (fp16, gelu)
    dim3 gxy(NGATE / 256, TOK / 128);   // (20, 64)
    gemm_f16<<<gxy, 256, GSMEM>>>(p_xh, p_wch, b_x, b_y, nullptr, nullptr,
                                  DDIM, DDIM, 0, 1);

    // conv (fp16 in, fp16 out)
    conv_kernel<<<(2 * (SEQB / 4) * (DDIM / 4) + 255) / 256, 256>>>(conv_w, conv_b);

    // gates GEMM (interleaved ig/ag) + fused RG-LRU pointwise + scan phase 1
    gemm_f16<<<gxy, 256, GSMEM>>>(p_coh, p_gwh, ig_b, ag_b, a_param, nullptr,
                                  BW, BW, 0, 2);

    // cross-chunk scan + fix-up
    scan_phase2<<<(2 * DDIM + 255) / 256, 256>>>(prev_h);
    scan_phase3<<<dim3(DDIM / 256, NC, 2), 256>>>();

    // final GEMM
    dim3 gf(DDIM / 256, TOK / 128);     // (10, 64)
    gemm_f16<<<gf, 256, GSMEM>>>(p_nxh, p_woh, b_out, nullptr, nullptr, out,
                                 DDIM, DDIM, DDIM, 0);
}